// round 2
// baseline (speedup 1.0000x reference)
#include <cuda_runtime.h>
#include <math.h>

// Problem constants
#define BATCH   8192
#define IN_DIM  4096
#define OUT_DIM 2048
#define DEPTH   9
#define RSTEPS  27          // 3 gates * 9 depths
#define WIN     55          // 2*RSTEPS + 1 dependency window
#define CENTER  27

// probs[o] + bias[o], precomputed by probs_kernel, consumed by GEMM epilogue.
__device__ float g_pb[OUT_DIM];

// ---------------------------------------------------------------------------
// Kernel 1: universal probs (window-cone trick).
// s_next[i] = cos(a)*s[i] - sin(a)*s[i+1] + sin(a)*s[i-1] (circulant, n=4096).
// Only s[0] after 27 steps matters -> track indices [-27, 27]. Window edges go
// stale after step 1 but contamination moves 1 cell/step; it reaches the
// center only at step 28, so 27 steps leave w[CENTER] exact.
// ---------------------------------------------------------------------------
__global__ void probs_kernel(const float* __restrict__ uw,
                             const float* __restrict__ bias) {
    int o = blockIdx.x * blockDim.x + threadIdx.x;
    if (o >= OUT_DIM) return;

    float w[WIN];
#pragma unroll
    for (int j = 0; j < WIN; j++) w[j] = 0.015625f;   // 1/sqrt(4096)

#pragma unroll
    for (int t = 0; t < RSTEPS; t++) {
        const int d = t / 3;
        const int g = t % 3;
        // A[t, o] = universal_weights[d, o, g]; layout (DEPTH, IN_DIM, OUT_DIM)
        float ang = uw[(size_t)d * IN_DIM * OUT_DIM + (size_t)o * OUT_DIM + g];
        float s, c;
        sincosf(ang, &s, &c);
        float nw[WIN];
        nw[0]       = w[0];
        nw[WIN - 1] = w[WIN - 1];
#pragma unroll
        for (int j = 1; j < WIN - 1; j++)
            nw[j] = c * w[j] - s * w[j + 1] + s * w[j - 1];
#pragma unroll
        for (int j = 0; j < WIN; j++) w[j] = nw[j];
    }
    float p = w[CENTER] * w[CENTER];
    g_pb[o] = p + bias[o];
}

// ---------------------------------------------------------------------------
// Kernel 2: C = tanh(x @ W + g_pb), fp32 SIMT GEMM.
// 128x128x16 tiles, 256 threads, 8x8 per-thread, double-buffered smem,
// register-staged global prefetch, one __syncthreads per K-tile.
// ---------------------------------------------------------------------------
#define BM 128
#define BN 128
#define BK 16

__global__ __launch_bounds__(256)
void gemm_tanh_kernel(const float* __restrict__ A,   // [BATCH, IN_DIM]
                      const float* __restrict__ W,   // [IN_DIM, OUT_DIM]
                      float* __restrict__ C) {       // [BATCH, OUT_DIM]
    __shared__ float As[2][BK][BM];   // K-major (transposed) for broadcast reads
    __shared__ float Bs[2][BK][BN];

    const int tid = threadIdx.x;
    const int bm  = blockIdx.y * BM;
    const int bn  = blockIdx.x * BN;

    // Global-load mapping: A tile = 128 rows x 16 cols -> 512 float4, 2/thread
    const int arow = tid >> 2;            // 0..63
    const int acol = (tid & 3) << 2;      // 0,4,8,12
    // W tile = 16 rows x 128 cols -> 512 float4, 2/thread
    const int brow = tid >> 5;            // 0..7
    const int bcol = (tid & 31) << 2;     // 0..124

    const float* Ab = A + (size_t)bm * IN_DIM;
    const float* Wb = W + bn;

    float4 a0, a1, b0, b1;

    // Prologue: tile 0 -> smem buffer 0
    a0 = *(const float4*)(Ab + (size_t)arow        * IN_DIM + acol);
    a1 = *(const float4*)(Ab + (size_t)(arow + 64) * IN_DIM + acol);
    b0 = *(const float4*)(Wb + (size_t)brow        * OUT_DIM + bcol);
    b1 = *(const float4*)(Wb + (size_t)(brow + 8)  * OUT_DIM + bcol);
    As[0][acol + 0][arow]      = a0.x;
    As[0][acol + 1][arow]      = a0.y;
    As[0][acol + 2][arow]      = a0.z;
    As[0][acol + 3][arow]      = a0.w;
    As[0][acol + 0][arow + 64] = a1.x;
    As[0][acol + 1][arow + 64] = a1.y;
    As[0][acol + 2][arow + 64] = a1.z;
    As[0][acol + 3][arow + 64] = a1.w;
    *(float4*)&Bs[0][brow][bcol]     = b0;
    *(float4*)&Bs[0][brow + 8][bcol] = b1;
    __syncthreads();

    const int tm0 = (tid >> 4) << 3;   // 0..120 step 8
    const int tn0 = (tid & 15) << 3;   // 0..120 step 8

    float acc[8][8];
#pragma unroll
    for (int i = 0; i < 8; i++)
#pragma unroll
        for (int j = 0; j < 8; j++) acc[i][j] = 0.0f;

    int buf = 0;
    const int NKT = IN_DIM / BK;       // 256
    for (int kt = 0; kt < NKT; kt++) {
        // Prefetch next tile into registers
        if (kt + 1 < NKT) {
            const float* An = Ab + (kt + 1) * BK;
            a0 = *(const float4*)(An + (size_t)arow        * IN_DIM + acol);
            a1 = *(const float4*)(An + (size_t)(arow + 64) * IN_DIM + acol);
            const float* Wn = Wb + (size_t)(kt + 1) * BK * OUT_DIM;
            b0 = *(const float4*)(Wn + (size_t)brow       * OUT_DIM + bcol);
            b1 = *(const float4*)(Wn + (size_t)(brow + 8) * OUT_DIM + bcol);
        }
        // Compute on current buffer
#pragma unroll
        for (int k = 0; k < BK; k++) {
            float af[8], bf[8];
            *(float4*)&af[0] = *(const float4*)&As[buf][k][tm0];
            *(float4*)&af[4] = *(const float4*)&As[buf][k][tm0 + 4];
            *(float4*)&bf[0] = *(const float4*)&Bs[buf][k][tn0];
            *(float4*)&bf[4] = *(const float4*)&Bs[buf][k][tn0 + 4];
#pragma unroll
            for (int i = 0; i < 8; i++)
#pragma unroll
                for (int j = 0; j < 8; j++)
                    acc[i][j] = fmaf(af[i], bf[j], acc[i][j]);
        }
        // Stage next tile into the other buffer (safe: that buffer was fully
        // consumed before the previous __syncthreads)
        if (kt + 1 < NKT) {
            const int nb = buf ^ 1;
            As[nb][acol + 0][arow]      = a0.x;
            As[nb][acol + 1][arow]      = a0.y;
            As[nb][acol + 2][arow]      = a0.z;
            As[nb][acol + 3][arow]      = a0.w;
            As[nb][acol + 0][arow + 64] = a1.x;
            As[nb][acol + 1][arow + 64] = a1.y;
            As[nb][acol + 2][arow + 64] = a1.z;
            As[nb][acol + 3][arow + 64] = a1.w;
            *(float4*)&Bs[nb][brow][bcol]     = b0;
            *(float4*)&Bs[nb][brow + 8][bcol] = b1;
        }
        __syncthreads();
        buf ^= 1;
    }

    // Epilogue: + (probs + bias), tanh, store
    float pb[8];
#pragma unroll
    for (int j = 0; j < 8; j++) pb[j] = g_pb[bn + tn0 + j];

#pragma unroll
    for (int i = 0; i < 8; i++) {
        const int row = bm + tm0 + i;
        float4 o0, o1;
        o0.x = tanhf(acc[i][0] + pb[0]);
        o0.y = tanhf(acc[i][1] + pb[1]);
        o0.z = tanhf(acc[i][2] + pb[2]);
        o0.w = tanhf(acc[i][3] + pb[3]);
        o1.x = tanhf(acc[i][4] + pb[4]);
        o1.y = tanhf(acc[i][5] + pb[5]);
        o1.z = tanhf(acc[i][6] + pb[6]);
        o1.w = tanhf(acc[i][7] + pb[7]);
        *(float4*)&C[(size_t)row * OUT_DIM + bn + tn0]     = o0;
        *(float4*)&C[(size_t)row * OUT_DIM + bn + tn0 + 4] = o1;
    }
}

// ---------------------------------------------------------------------------
// Launch. Inputs identified by element count (robust to metadata ordering):
//   x  : 8192*4096  = 33554432
//   uw : 9*4096*2048= 75497472
//   cw : 4096*2048  =  8388608
//   cb : 2048
// ---------------------------------------------------------------------------
extern "C" void kernel_launch(void* const* d_in, const int* in_sizes, int n_in,
                              void* d_out, int out_size) {
    const float* x  = nullptr;
    const float* uw = nullptr;
    const float* cw = nullptr;
    const float* cb = nullptr;
    for (int i = 0; i < n_in; i++) {
        switch (in_sizes[i]) {
            case BATCH * IN_DIM:           x  = (const float*)d_in[i]; break;
            case DEPTH * IN_DIM * OUT_DIM: uw = (const float*)d_in[i]; break;
            case IN_DIM * OUT_DIM:         cw = (const float*)d_in[i]; break;
            case OUT_DIM:                  cb = (const float*)d_in[i]; break;
            default: break;
        }
    }
    float* out = (float*)d_out;

    probs_kernel<<<OUT_DIM / 256, 256>>>(uw, cb);

    dim3 grid(OUT_DIM / BN, BATCH / BM);   // (16, 64)
    gemm_tanh_kernel<<<grid, 256>>>(x, cw, out);
}

// round 4
// speedup vs baseline: 2.4729x; 2.4729x over previous
#include <cuda_runtime.h>
#include <cuda_bf16.h>
#include <math.h>
#include <stdint.h>

// ---------------------------------------------------------------------------
// Problem constants
// ---------------------------------------------------------------------------
#define BATCH   8192
#define IN_DIM  4096
#define OUT_DIM 2048
#define DEPTH   9
#define RSTEPS  27
#define WIN     55
#define CENTER  27

// GEMM tiling
#define BM 128
#define BN 128
#define BK 32
#define NKT (IN_DIM / BK)          // 128
#define STAGES 3
#define MAT_BYTES 8192             // one 128x32 bf16 tile
#define STAGE_BYTES (4 * MAT_BYTES)  // Ahi, Alo, Bhi, Blo
#define SMEM_TOTAL (STAGES * STAGE_BYTES)  // 98304

#define AHI 0
#define ALO 8192
#define BHI 16384
#define BLO 24576

// ---------------------------------------------------------------------------
// Device-global scratch (static: no runtime allocation)
// ---------------------------------------------------------------------------
__device__ float         g_pb[OUT_DIM];
__device__ __nv_bfloat16 g_xhi[(size_t)BATCH * IN_DIM];
__device__ __nv_bfloat16 g_xlo[(size_t)BATCH * IN_DIM];
__device__ __nv_bfloat16 g_wThi[(size_t)OUT_DIM * IN_DIM];   // W^T [N][K]
__device__ __nv_bfloat16 g_wTlo[(size_t)OUT_DIM * IN_DIM];

// ---------------------------------------------------------------------------
// PTX helpers (base sm_103 ISA only: cp.async / ldmatrix / mma.sync)
// ---------------------------------------------------------------------------
__device__ __forceinline__ uint32_t smem_u32(const void* p) {
    uint32_t a;
    asm("{ .reg .u64 t; cvta.to.shared.u64 t, %1; cvt.u32.u64 %0, t; }"
        : "=r"(a) : "l"(p));
    return a;
}
__device__ __forceinline__ void cpasync16(uint32_t dst, const void* src) {
    asm volatile("cp.async.cg.shared.global [%0], [%1], 16;"
                 :: "r"(dst), "l"(src));
}
#define CP_COMMIT() asm volatile("cp.async.commit_group;" ::: "memory")
#define CP_WAIT1()  asm volatile("cp.async.wait_group 1;"  ::: "memory")

#define LDSM_X4(d, a) \
    asm volatile("ldmatrix.sync.aligned.m8n8.x4.shared.b16 {%0,%1,%2,%3}, [%4];" \
        : "=r"((d)[0]), "=r"((d)[1]), "=r"((d)[2]), "=r"((d)[3]) : "r"(a))
#define LDSM_X2(d, a) \
    asm volatile("ldmatrix.sync.aligned.m8n8.x2.shared.b16 {%0,%1}, [%2];" \
        : "=r"((d)[0]), "=r"((d)[1]) : "r"(a))

#define MMA16816(c, a, b) \
    asm volatile("mma.sync.aligned.m16n8k16.row.col.f32.bf16.bf16.f32 " \
        "{%0,%1,%2,%3}, {%4,%5,%6,%7}, {%8,%9}, {%0,%1,%2,%3};" \
        : "+f"((c)[0]), "+f"((c)[1]), "+f"((c)[2]), "+f"((c)[3]) \
        : "r"((a)[0]), "r"((a)[1]), "r"((a)[2]), "r"((a)[3]), \
          "r"((b)[0]), "r"((b)[1]))

// Swizzled smem offset for logical (row 0..127, 16B-chunk cc 0..3).
// Physical layout: 64 rows x 128B; chunk8 = ((row&1)<<2)|cc, XOR p&7.
// Any 8 consecutive logical rows at fixed cc hit 8 distinct chunks.
__device__ __forceinline__ uint32_t swz(uint32_t base, int row, int cc) {
    int p  = row >> 1;
    int c8 = ((row & 1) << 2) | cc;
    return base + p * 128 + (((c8 ^ (p & 7))) << 4);
}

// ---------------------------------------------------------------------------
// Kernel 1: universal probs (dependency-cone trick) + bias -> g_pb
// ---------------------------------------------------------------------------
__global__ void probs_kernel(const float* __restrict__ uw,
                             const float* __restrict__ bias) {
    int o = blockIdx.x * blockDim.x + threadIdx.x;
    if (o >= OUT_DIM) return;
    float w[WIN];
#pragma unroll
    for (int j = 0; j < WIN; j++) w[j] = 0.015625f;   // 1/sqrt(4096)
#pragma unroll
    for (int t = 0; t < RSTEPS; t++) {
        const int d = t / 3, g = t % 3;
        float ang = uw[(size_t)d * IN_DIM * OUT_DIM + (size_t)o * OUT_DIM + g];
        float s, c;
        sincosf(ang, &s, &c);
        float nw[WIN];
        nw[0] = w[0]; nw[WIN - 1] = w[WIN - 1];
#pragma unroll
        for (int j = 1; j < WIN - 1; j++)
            nw[j] = c * w[j] - s * w[j + 1] + s * w[j - 1];
#pragma unroll
        for (int j = 0; j < WIN; j++) w[j] = nw[j];
    }
    g_pb[o] = w[CENTER] * w[CENTER] + bias[o];
}

// ---------------------------------------------------------------------------
// Kernel 2: split x -> (hi, lo) bf16
// ---------------------------------------------------------------------------
__global__ void split_x_kernel(const float* __restrict__ x) {
    size_t i = ((size_t)blockIdx.x * blockDim.x + threadIdx.x) * 4;
    float4 v = *(const float4*)(x + i);
    __nv_bfloat16 h0 = __float2bfloat16(v.x);
    __nv_bfloat16 h1 = __float2bfloat16(v.y);
    __nv_bfloat16 h2 = __float2bfloat16(v.z);
    __nv_bfloat16 h3 = __float2bfloat16(v.w);
    __nv_bfloat162* ph = (__nv_bfloat162*)(g_xhi + i);
    __nv_bfloat162* pl = (__nv_bfloat162*)(g_xlo + i);
    ph[0] = __nv_bfloat162(h0, h1);
    ph[1] = __nv_bfloat162(h2, h3);
    pl[0] = __nv_bfloat162(__float2bfloat16(v.x - __bfloat162float(h0)),
                           __float2bfloat16(v.y - __bfloat162float(h1)));
    pl[1] = __nv_bfloat162(__float2bfloat16(v.z - __bfloat162float(h2)),
                           __float2bfloat16(v.w - __bfloat162float(h3)));
}

// ---------------------------------------------------------------------------
// Kernel 3: transpose + split W[k][n] -> wT_hi/lo[n][k]
// ---------------------------------------------------------------------------
__global__ void split_w_kernel(const float* __restrict__ W) {
    __shared__ float t[32][33];
    const int n0 = blockIdx.x * 32, k0 = blockIdx.y * 32;
    const int tx = threadIdx.x, ty = threadIdx.y;   // 32 x 8
#pragma unroll
    for (int i = 0; i < 32; i += 8)
        t[ty + i][tx] = W[(size_t)(k0 + ty + i) * OUT_DIM + n0 + tx];
    __syncthreads();
#pragma unroll
    for (int i = 0; i < 32; i += 8) {
        float v = t[tx][ty + i];
        __nv_bfloat16 h = __float2bfloat16(v);
        size_t o = (size_t)(n0 + ty + i) * IN_DIM + k0 + tx;
        g_wThi[o] = h;
        g_wTlo[o] = __float2bfloat16(v - __bfloat162float(h));
    }
}

// ---------------------------------------------------------------------------
// Kernel 4: C = tanh(x @ W + g_pb) via bf16x3 mma.sync GEMM.
// 128x128x32 CTA tile, 8 warps (2x4), warp tile 64x32, 3-stage cp.async.
// ---------------------------------------------------------------------------
__global__ __launch_bounds__(256, 1)
void gemm_bf16x3_kernel(float* __restrict__ out) {
    extern __shared__ char smem[];
    const uint32_t sb = smem_u32(smem);

    const int tid  = threadIdx.x;
    const int lane = tid & 31;
    const int wid  = tid >> 5;
    const int wm   = wid >> 2;          // 0..1  -> m offset wm*64
    const int wn   = wid & 3;           // 0..3  -> n offset wn*32
    const int gid  = lane >> 2;
    const int tg   = lane & 3;
    const int bm   = blockIdx.y * BM;
    const int bn   = blockIdx.x * BN;

    // --- global load mapping: 2048 x 16B chunks/stage, 8 per thread ---
    // chunk id c in [0,512) per matrix; this thread owns c = tid and tid+256.
    const int rA = tid >> 2;            // rows 0..63 (chunk tid)
    const int rB = 64 + (tid >> 2);     // rows 64..127 (chunk tid+256)
    const int cc = tid & 3;

    const __nv_bfloat16* pA0h = g_xhi  + (size_t)(bm + rA) * IN_DIM + cc * 8;
    const __nv_bfloat16* pA1h = g_xhi  + (size_t)(bm + rB) * IN_DIM + cc * 8;
    const __nv_bfloat16* pA0l = g_xlo  + (size_t)(bm + rA) * IN_DIM + cc * 8;
    const __nv_bfloat16* pA1l = g_xlo  + (size_t)(bm + rB) * IN_DIM + cc * 8;
    const __nv_bfloat16* pB0h = g_wThi + (size_t)(bn + rA) * IN_DIM + cc * 8;
    const __nv_bfloat16* pB1h = g_wThi + (size_t)(bn + rB) * IN_DIM + cc * 8;
    const __nv_bfloat16* pB0l = g_wTlo + (size_t)(bn + rA) * IN_DIM + cc * 8;
    const __nv_bfloat16* pB1l = g_wTlo + (size_t)(bn + rB) * IN_DIM + cc * 8;

    const uint32_t dA0 = swz(AHI, rA, cc), dA1 = swz(AHI, rB, cc);
    const uint32_t dL0 = swz(ALO, rA, cc), dL1 = swz(ALO, rB, cc);
    const uint32_t dB0 = swz(BHI, rA, cc), dB1 = swz(BHI, rB, cc);
    const uint32_t dC0 = swz(BLO, rA, cc), dC1 = swz(BLO, rB, cc);

    int kload = 0;   // next k offset (elements) to issue
#define ISSUE_STAGE(stg)                                                     \
    do {                                                                     \
        uint32_t s_ = sb + (stg) * STAGE_BYTES;                              \
        cpasync16(s_ + dA0, pA0h + kload);                                   \
        cpasync16(s_ + dA1, pA1h + kload);                                   \
        cpasync16(s_ + dL0, pA0l + kload);                                   \
        cpasync16(s_ + dL1, pA1l + kload);                                   \
        cpasync16(s_ + dB0, pB0h + kload);                                   \
        cpasync16(s_ + dB1, pB1h + kload);                                   \
        cpasync16(s_ + dC0, pB0l + kload);                                   \
        cpasync16(s_ + dC1, pB1l + kload);                                   \
        kload += BK;                                                         \
    } while (0)

    // Prologue: stages 0 and 1
    ISSUE_STAGE(0); CP_COMMIT();
    ISSUE_STAGE(1); CP_COMMIT();

    float acc[4][4][4];
#pragma unroll
    for (int i = 0; i < 4; i++)
#pragma unroll
        for (int j = 0; j < 4; j++)
#pragma unroll
            for (int q = 0; q < 4; q++) acc[i][j][q] = 0.0f;

    // Per-lane ldmatrix logical coordinates
    const int a_rl  = lane & 15;          // A: rows m0..m0+15
    const int a_ch  = lane >> 4;          // A: +0 / +1 chunk
    const int b_rl  = lane & 7;           // B: rows n0..n0+7
    const int b_ch  = (lane >> 3) & 1;    // B: +0 / +1 chunk

    int stage = 0;
#pragma unroll 1
    for (int kt = 0; kt < NKT; kt++) {
        CP_WAIT1();
        __syncthreads();

        // Issue loads for kt+2 into the stage being freed
        if (kt + 2 < NKT) {
            int nst = stage + 2; if (nst >= STAGES) nst -= STAGES;
            ISSUE_STAGE(nst);
        }
        CP_COMMIT();

        const uint32_t s_ = sb + stage * STAGE_BYTES;

#pragma unroll
        for (int ks = 0; ks < 2; ks++) {
            uint32_t ah[4][4], al[4][4], bh[4][2], bl[4][2];
            const int ccA = ks * 2 + a_ch;
            const int ccB = ks * 2 + b_ch;
#pragma unroll
            for (int mi = 0; mi < 4; mi++) {
                const int row = wm * 64 + mi * 16 + a_rl;
                LDSM_X4(ah[mi], swz(s_ + AHI, row, ccA));
                LDSM_X4(al[mi], swz(s_ + ALO, row, ccA));
            }
#pragma unroll
            for (int ni = 0; ni < 4; ni++) {
                const int row = wn * 32 + ni * 8 + b_rl;
                LDSM_X2(bh[ni], swz(s_ + BHI, row, ccB));
                LDSM_X2(bl[ni], swz(s_ + BLO, row, ccB));
            }
#pragma unroll
            for (int mi = 0; mi < 4; mi++)
#pragma unroll
                for (int ni = 0; ni < 4; ni++) {
                    MMA16816(acc[mi][ni], ah[mi], bh[ni]);
                    MMA16816(acc[mi][ni], ah[mi], bl[ni]);
                    MMA16816(acc[mi][ni], al[mi], bh[ni]);
                }
        }
        stage++; if (stage >= STAGES) stage = 0;
    }

    // ------------------- epilogue: +pb, tanh, store -------------------
    float pbv[4][2];
#pragma unroll
    for (int ni = 0; ni < 4; ni++) {
        const int col = bn + wn * 32 + ni * 8 + tg * 2;
        pbv[ni][0] = g_pb[col];
        pbv[ni][1] = g_pb[col + 1];
    }
#pragma unroll
    for (int mi = 0; mi < 4; mi++) {
        const int r0 = bm + wm * 64 + mi * 16 + gid;
#pragma unroll
        for (int ni = 0; ni < 4; ni++) {
            const int col = bn + wn * 32 + ni * 8 + tg * 2;
            float2 v0, v1;
            v0.x = tanhf(acc[mi][ni][0] + pbv[ni][0]);
            v0.y = tanhf(acc[mi][ni][1] + pbv[ni][1]);
            v1.x = tanhf(acc[mi][ni][2] + pbv[ni][0]);
            v1.y = tanhf(acc[mi][ni][3] + pbv[ni][1]);
            *(float2*)(out + (size_t)r0 * OUT_DIM + col)       = v0;
            *(float2*)(out + (size_t)(r0 + 8) * OUT_DIM + col) = v1;
        }
    }
}

// ---------------------------------------------------------------------------
// Host launch
// ---------------------------------------------------------------------------
extern "C" void kernel_launch(void* const* d_in, const int* in_sizes, int n_in,
                              void* d_out, int out_size) {
    const float *x = nullptr, *uw = nullptr, *cw = nullptr, *cb = nullptr;
    for (int i = 0; i < n_in; i++) {
        switch (in_sizes[i]) {
            case BATCH * IN_DIM:           x  = (const float*)d_in[i]; break;
            case DEPTH * IN_DIM * OUT_DIM: uw = (const float*)d_in[i]; break;
            case IN_DIM * OUT_DIM:         cw = (const float*)d_in[i]; break;
            case OUT_DIM:                  cb = (const float*)d_in[i]; break;
            default: break;
        }
    }
    float* out = (float*)d_out;

    probs_kernel<<<OUT_DIM / 256, 256>>>(uw, cb);
    split_x_kernel<<<(BATCH * IN_DIM) / (4 * 256), 256>>>(x);
    split_w_kernel<<<dim3(OUT_DIM / 32, IN_DIM / 32), dim3(32, 8)>>>(cw);

    static int attr_done = 0;
    if (!attr_done) {
        cudaFuncSetAttribute(gemm_bf16x3_kernel,
                             cudaFuncAttributeMaxDynamicSharedMemorySize,
                             SMEM_TOTAL);
        attr_done = 1;
    }
    dim3 grid(OUT_DIM / BN, BATCH / BM);   // (16, 64)
    gemm_bf16x3_kernel<<<grid, 256, SMEM_TOTAL>>>(out);
}